// round 10
// baseline (speedup 1.0000x reference)
#include <cuda_runtime.h>
#include <cuda_bf16.h>
#include <cstdint>

// EmbeddingBagCollection: F=8 tables [N=200000, D=64] f32, values [F, T=163840] i32,
// offsets [F, B+1=8193] i32. Output [B=8192, F*D=512] f32.
//
// R10: DRAM-order prefetch. Hypothesis: the ~3.4 TB/s ceiling seen by R5/R9 is
// the HBM row-activate limit of random 256B reads (dram active only 43%).
//  - L0a/L0b: build a touched-row bitmap (F x 6250 words) from values.
//  - L1 fused kernel, staged grid [sweep f][gather f-1] (1:4 interleaved):
//      * sweep blocks walk the bitmap ASCENDING, issuing discard ld.global.cg
//        loads of marked rows -> activation-friendly DRAM order, warms L2
//        (28.6 MB unique/feature << 126 MB L2).
//      * gather blocks = the proven R5 bag-per-warp body (pair-loaded LDG.128,
//        predicated 16-pair burst) for the feature swept one stage earlier ->
//        random reads become L2 hits.
//  Sweep is advisory only; correctness = R5's. Deterministic (bitmap rebuilt
//  each call), graph-capturable (3 plain launches), no allocations
//  (__device__ global bitmap).

static constexpr int F = 8;
static constexpr int B = 8192;
static constexpr int N = 200000;
static constexpr int D = 64;
static constexpr int T = 163840;
static constexpr unsigned FULL = 0xffffffffu;

static constexpr int WORDS_PF      = N / 32;          // 6250 (N divisible by 32)
static constexpr int SWEEP_BLOCKS  = 256;             // per feature (250 active)
static constexpr int WORDS_PB      = 25;              // words per sweep block
static constexpr int GATHER_BLOCKS = B / 8;           // 1024 per feature
static constexpr int STAGE_W       = SWEEP_BLOCKS + GATHER_BLOCKS;  // 1280
static constexpr int TOTAL_BLOCKS  = SWEEP_BLOCKS + 7 * STAGE_W + GATHER_BLOCKS; // 10240

__device__ unsigned g_bitmap[F * WORDS_PF];           // 200 KB scratch

__global__ __launch_bounds__(256)
void ebc_zero_bitmap()
{
    const int i = blockIdx.x * blockDim.x + threadIdx.x;
    if (i < F * WORDS_PF) g_bitmap[i] = 0u;
}

__global__ __launch_bounds__(256)
void ebc_build_bitmap(const int* __restrict__ values)
{
    const int f = blockIdx.y;
    const int i = blockIdx.x * blockDim.x + threadIdx.x;   // i in [0, T)
    const int v = __ldg(values + (size_t)f * T + i);
    atomicOr(&g_bitmap[f * WORDS_PF + (v >> 5)], 1u << (v & 31));
}

__global__ __launch_bounds__(256, 4)
void ebc_fused_kernel(const float* __restrict__ tables,
                      const int*   __restrict__ values,
                      const int*   __restrict__ offsets,
                      float*       __restrict__ out)
{
    const int bid  = blockIdx.x;
    const int wib  = threadIdx.x >> 5;
    const int lane = threadIdx.x & 31;
    const int half = lane >> 4;          // 0: even rows, 1: odd rows
    const int hl   = lane & 15;          // 16B slot within a 256B row

    // ---- decode staged grid: [sweep f0][sweep f1|gather f0]...[gather f7] ----
    bool is_sweep;
    int f, idx;
    if (bid < SWEEP_BLOCKS) {
        is_sweep = true; f = 0; idx = bid;
    } else if (bid < SWEEP_BLOCKS + 7 * STAGE_W) {
        const int t = bid - SWEEP_BLOCKS;
        const int s = t / STAGE_W;                 // 0..6 -> stage s+1
        const int r = t - s * STAGE_W;             // 0..1279
        if (r % 5 == 0) { is_sweep = true;  f = s + 1; idx = r / 5; }
        else            { is_sweep = false; f = s;     idx = r - r / 5 - 1; }
    } else {
        is_sweep = false; f = 7; idx = bid - (SWEEP_BLOCKS + 7 * STAGE_W);
    }

    const float4* __restrict__ tab4 =
        reinterpret_cast<const float4*>(tables + (size_t)f * N * D);  // 16 float4/row

    if (is_sweep) {
        // ---- sweep: ascending discard-loads of marked rows (warms L2) ----
        const int wbeg = idx * WORDS_PB;
        if (wbeg >= WORDS_PF) return;
        const int wend = min(wbeg + WORDS_PB, WORDS_PF);
        for (int w = wbeg + wib; w < wend; w += 8) {
            const unsigned bm = __ldg(&g_bitmap[f * WORDS_PF + w]);
            if (bm == 0u) continue;
            const int rbase = w * 32;
#pragma unroll
            for (int p = 0; p < 16; ++p) {
                const int rp = 2 * p + half;
                if ((bm >> rp) & 1u) {
                    const float4* g = tab4 + (size_t)(rbase + rp) * 16 + hl;
                    unsigned a0, a1, a2, a3;
                    asm volatile("ld.global.cg.v4.b32 {%0,%1,%2,%3}, [%4];"
                                 : "=r"(a0), "=r"(a1), "=r"(a2), "=r"(a3)
                                 : "l"(g));
                    (void)a0; (void)a1; (void)a2; (void)a3;
                }
            }
        }
        return;
    }

    // ---- gather: R5 body, one warp per bag ----
    const int b = idx * 8 + wib;

    const int* __restrict__ offs = offsets + f * (B + 1);
    const int start = __ldg(offs + b);
    const int end   = __ldg(offs + b + 1);

    const int* __restrict__ vals = values + (size_t)f * T;

    float4 acc = make_float4(0.f, 0.f, 0.f, 0.f);

    int i = start;
    while (i < end) {
        const int rem   = end - i;
        const int chunk = rem < 32 ? rem : 32;

        const int src = lane < chunk ? lane : 0;
        const int idxv = __ldg(vals + i + src);      // coalesced index prefetch

#pragma unroll
        for (int p = 0; p < 16; ++p) {
            const int rp = 2 * p + half;             // row position in chunk
            const int r  = __shfl_sync(FULL, idxv, rp & 31);
            if (rp < chunk) {
                const float4 v = __ldg(tab4 + (size_t)r * 16 + hl);
                acc.x += v.x; acc.y += v.y; acc.z += v.z; acc.w += v.w;
            }
        }
        i += chunk;
    }

    // Merge even/odd-row partial sums across half-warps.
    acc.x += __shfl_xor_sync(FULL, acc.x, 16);
    acc.y += __shfl_xor_sync(FULL, acc.y, 16);
    acc.z += __shfl_xor_sync(FULL, acc.z, 16);
    acc.w += __shfl_xor_sync(FULL, acc.w, 16);

    // Lanes 0-15 store one coalesced 256B row (empty bags write zeros).
    if (lane < 16) {
        float4* __restrict__ o =
            reinterpret_cast<float4*>(out + (size_t)b * (F * D) + f * D);
        o[hl] = acc;
    }
}

extern "C" void kernel_launch(void* const* d_in, const int* in_sizes, int n_in,
                              void* d_out, int out_size)
{
    const float* tables  = (const float*)d_in[0];  // [F, N, D]
    const int*   values  = (const int*)  d_in[1];  // [F, T]
    const int*   offsets = (const int*)  d_in[2];  // [F, B+1]
    float*       out     = (float*)d_out;          // [B, F*D]

    // L0a: zero bitmap (rebuilt every call -> deterministic).
    const int nw = F * WORDS_PF;
    ebc_zero_bitmap<<<(nw + 255) / 256, 256>>>();

    // L0b: mark touched rows.
    ebc_build_bitmap<<<dim3(T / 256, F), 256>>>(values);

    // L1: staged sweep+gather.
    ebc_fused_kernel<<<TOTAL_BLOCKS, 256>>>(tables, values, offsets, out);
}

// round 11
// speedup vs baseline: 1.1284x; 1.1284x over previous
#include <cuda_runtime.h>
#include <cuda.h>
#include <cuda_bf16.h>
#include <cstdint>

// EmbeddingBagCollection: F=8 tables [N=200000, D=64] f32, values [F, T=163840] i32,
// offsets [F, B+1=8193] i32. Output [B=8192, F*D=512] f32.
//
// R11: TMA-path gather. Theory: all LDG/cp.async variants cap at ~3.4 TB/s
// because per-SM L1tex outstanding-miss capacity (~14 KB in flight) binds.
// TMA bulk-tensor loads use the dedicated engine (UTMALDG), bypassing L1tex.
//  - One warp per (f, b) bag; 32-row chunks.
//  - Each lane issues one 256B TMA 2D tile load (box {64,1}) of its own row
//    into a per-warp SMEM buffer; mbarrier expect_tx = chunk*256.
//  - LDS readback (pair layout), shfl_xor(16) merge, one 256B store per bag.
//  - Tensormap encoded host-side via cudaGetDriverEntryPointByVersion (no
//    -lcuda link dep), passed __grid_constant__. On any failure: fall back to
//    the proven R9 cp.async kernel (73.9us).

static constexpr int F = 8;
static constexpr int B = 8192;
static constexpr int N = 200000;
static constexpr int D = 64;
static constexpr int T = 163840;
static constexpr unsigned FULL = 0xffffffffu;

static constexpr int WPB       = 4;                  // warps per block
static constexpr int CHUNK     = 32;                 // rows staged per burst
static constexpr int ROW_BYTES = D * 4;              // 256
static constexpr int BUF_BYTES = CHUNK * ROW_BYTES;  // 8 KB per warp

// ---------------------------------------------------------------------------
// TMA kernel
// ---------------------------------------------------------------------------
__global__ __launch_bounds__(WPB * 32)
void ebc_tma_kernel(const __grid_constant__ CUtensorMap tmap,
                    const int*   __restrict__ values,
                    const int*   __restrict__ offsets,
                    float*       __restrict__ out)
{
    __shared__ alignas(1024) float4   sbuf[WPB][CHUNK * 16];  // 8 KB per warp
    __shared__ alignas(8)    uint64_t smbar[WPB];

    const int wib   = threadIdx.x >> 5;
    const int lane  = threadIdx.x & 31;
    const int gwarp = blockIdx.x * WPB + wib;        // grid sized exactly F*B

    const int f = gwarp >> 13;                       // B = 8192 = 2^13
    const int b = gwarp & (B - 1);

    const int half = lane >> 4;                      // 0: even rows, 1: odd
    const int hl   = lane & 15;                      // 16B slot within a row

    uint32_t mbar;
    {
        uint64_t a = (uint64_t)__cvta_generic_to_shared(&smbar[wib]);
        mbar = (uint32_t)a;
    }
    uint32_t bufs;
    {
        uint64_t a = (uint64_t)__cvta_generic_to_shared(&sbuf[wib][0]);
        bufs = (uint32_t)a;
    }

    if (lane == 0) {
        asm volatile("mbarrier.init.shared.b64 [%0], 1;" :: "r"(mbar) : "memory");
    }
    __syncwarp();
    asm volatile("fence.proxy.async.shared::cta;" ::: "memory");

    const int* __restrict__ offs = offsets + f * (B + 1);
    const int start = __ldg(offs + b);
    const int end   = __ldg(offs + b + 1);

    const int* __restrict__ vals = values + (size_t)f * T;
    const int ybase = f * N;

    float4 acc = make_float4(0.f, 0.f, 0.f, 0.f);

    int i = start;
    int phase = 0;
    while (i < end) {
        const int rem   = end - i;
        const int chunk = rem < CHUNK ? rem : CHUNK;

        // Protect buffer reuse across iterations (reads of prev chunk done).
        __syncwarp();
        asm volatile("fence.proxy.async.shared::cta;" ::: "memory");

        // Each active lane's own row index (coalesced load).
        const int src = lane < chunk ? lane : 0;
        const int row = __ldg(vals + i + src);

        if (lane == 0) {
            asm volatile("mbarrier.arrive.expect_tx.shared.b64 _, [%0], %1;"
                         :: "r"(mbar), "r"((unsigned)(chunk * ROW_BYTES))
                         : "memory");
        }
        if (lane < chunk) {
            const uint32_t dst = bufs + lane * ROW_BYTES;
            const int y = ybase + row;
            asm volatile(
                "cp.async.bulk.tensor.2d.shared::cta.global.tile"
                ".mbarrier::complete_tx::bytes [%0], [%1, {%2, %3}], [%4];"
                :: "r"(dst), "l"(&tmap), "r"(0), "r"(y), "r"(mbar)
                : "memory");
        }

        // Wait for all rows of this chunk.
        {
            unsigned done;
            asm volatile(
                "{\n\t.reg .pred p;\n\t"
                "mbarrier.try_wait.parity.acquire.cta.shared::cta.b64 p, [%1], %2;\n\t"
                "selp.b32 %0, 1, 0, p;\n\t}"
                : "=r"(done) : "r"(mbar), "r"((unsigned)phase) : "memory");
            if (!done) {
                asm volatile(
                    "{\n\t.reg .pred P1;\n\t"
                    "W_%=:\n\t"
                    "mbarrier.try_wait.parity.acquire.cta.shared::cta.b64 P1, [%0], %1, 0x989680;\n\t"
                    "@P1 bra.uni D_%=;\n\t"
                    "bra.uni W_%=;\n\t"
                    "D_%=:\n\t}"
                    :: "r"(mbar), "r"((unsigned)phase) : "memory");
            }
        }
        phase ^= 1;

        // Accumulate: half-warps take even/odd rows, lane = 16B slot.
#pragma unroll
        for (int p = 0; p < CHUNK / 2; ++p) {
            const int rp = 2 * p + half;
            if (rp < chunk) {
                const float4 v = sbuf[wib][rp * 16 + hl];
                acc.x += v.x; acc.y += v.y; acc.z += v.z; acc.w += v.w;
            }
        }
        i += chunk;
    }

    // Merge even/odd-row partial sums across half-warps.
    acc.x += __shfl_xor_sync(FULL, acc.x, 16);
    acc.y += __shfl_xor_sync(FULL, acc.y, 16);
    acc.z += __shfl_xor_sync(FULL, acc.z, 16);
    acc.w += __shfl_xor_sync(FULL, acc.w, 16);

    // Lanes 0-15 store one coalesced 256B row (empty bags write zeros).
    if (lane < 16) {
        float4* __restrict__ o =
            reinterpret_cast<float4*>(out + (size_t)b * (F * D) + f * D);
        o[hl] = acc;
    }
}

// ---------------------------------------------------------------------------
// Fallback: R9 cp.async kernel (proven 73.9us)
// ---------------------------------------------------------------------------
__global__ __launch_bounds__(WPB * 32)
void ebc_pool_kernel(const float* __restrict__ tables,
                     const int*   __restrict__ values,
                     const int*   __restrict__ offsets,
                     float*       __restrict__ out)
{
    extern __shared__ float4 dbuf[];                 // [WPB][CHUNK][16]

    const int wib   = threadIdx.x >> 5;
    const int lane  = threadIdx.x & 31;
    const int gwarp = blockIdx.x * WPB + wib;

    const int f = gwarp >> 13;
    const int b = gwarp & (B - 1);

    const int half = lane >> 4;
    const int hl   = lane & 15;

    const int* __restrict__ offs = offsets + f * (B + 1);
    const int start = __ldg(offs + b);
    const int end   = __ldg(offs + b + 1);

    const int* __restrict__ vals = values + (size_t)f * T;
    const float4* __restrict__ tab4 =
        reinterpret_cast<const float4*>(tables + (size_t)f * N * D);

    float4* __restrict__ bufg = dbuf + wib * (CHUNK * 16);
    const uint32_t buf_s =
        (uint32_t)__cvta_generic_to_shared(dbuf) + wib * BUF_BYTES;

    float4 acc = make_float4(0.f, 0.f, 0.f, 0.f);

    int i = start;
    while (i < end) {
        const int rem   = end - i;
        const int chunk = rem < CHUNK ? rem : CHUNK;

        const int src = lane < chunk ? lane : 0;
        const int idx = __ldg(vals + i + src);

#pragma unroll
        for (int p = 0; p < CHUNK / 2; ++p) {
            const int rp = 2 * p + half;
            const int r  = __shfl_sync(FULL, idx, rp & 31);
            if (rp < chunk) {
                const float4* g = tab4 + (size_t)r * 16 + hl;
                const uint32_t d = buf_s + rp * ROW_BYTES + hl * 16;
                asm volatile("cp.async.cg.shared.global [%0], [%1], 16;\n"
                             :: "r"(d), "l"(g) : "memory");
            }
        }
        asm volatile("cp.async.commit_group;\n" ::: "memory");
        asm volatile("cp.async.wait_group 0;\n" ::: "memory");

#pragma unroll
        for (int p = 0; p < CHUNK / 2; ++p) {
            const int rp = 2 * p + half;
            if (rp < chunk) {
                const float4 v = bufg[rp * 16 + hl];
                acc.x += v.x; acc.y += v.y; acc.z += v.z; acc.w += v.w;
            }
        }
        i += chunk;
    }

    acc.x += __shfl_xor_sync(FULL, acc.x, 16);
    acc.y += __shfl_xor_sync(FULL, acc.y, 16);
    acc.z += __shfl_xor_sync(FULL, acc.z, 16);
    acc.w += __shfl_xor_sync(FULL, acc.w, 16);

    if (lane < 16) {
        float4* __restrict__ o =
            reinterpret_cast<float4*>(out + (size_t)b * (F * D) + f * D);
        o[hl] = acc;
    }
}

// ---------------------------------------------------------------------------
// Host launcher
// ---------------------------------------------------------------------------
typedef CUresult (*PFN_encodeTiled)(
    CUtensorMap*, CUtensorMapDataType, cuuint32_t, void*,
    const cuuint64_t*, const cuuint64_t*, const cuuint32_t*, const cuuint32_t*,
    CUtensorMapInterleave, CUtensorMapSwizzle, CUtensorMapL2promotion,
    CUtensorMapFloatOOBfill);

extern "C" void kernel_launch(void* const* d_in, const int* in_sizes, int n_in,
                              void* d_out, int out_size)
{
    const float* tables  = (const float*)d_in[0];  // [F, N, D]
    const int*   values  = (const int*)  d_in[1];  // [F, T]
    const int*   offsets = (const int*)  d_in[2];  // [F, B+1]
    float*       out     = (float*)d_out;          // [B, F*D]

    const int blocks  = (F * B) / WPB;             // 16384
    const int threads = WPB * 32;                  // 128

    // Try to build a TMA descriptor: 2D [64 elems, F*N rows], 256B row stride.
    bool tma_ok = false;
    CUtensorMap tmap;
    {
        void* fn = nullptr;
        cudaDriverEntryPointQueryResult qr =
            cudaDriverEntryPointSymbolNotFound;
        if (cudaGetDriverEntryPointByVersion("cuTensorMapEncodeTiled", &fn,
                                             12000, cudaEnableDefault, &qr)
                == cudaSuccess && fn && qr == cudaDriverEntryPointSuccess) {
            cuuint64_t gdim[2] = {(cuuint64_t)D, (cuuint64_t)F * N};
            cuuint64_t gstr[1] = {(cuuint64_t)ROW_BYTES};
            cuuint32_t box[2]  = {(cuuint32_t)D, 1u};
            cuuint32_t estr[2] = {1u, 1u};
            CUresult r = ((PFN_encodeTiled)fn)(
                &tmap, CU_TENSOR_MAP_DATA_TYPE_FLOAT32, 2, (void*)tables,
                gdim, gstr, box, estr,
                CU_TENSOR_MAP_INTERLEAVE_NONE, CU_TENSOR_MAP_SWIZZLE_NONE,
                CU_TENSOR_MAP_L2_PROMOTION_L2_128B,
                CU_TENSOR_MAP_FLOAT_OOB_FILL_NONE);
            tma_ok = (r == CUDA_SUCCESS);
        }
    }

    if (tma_ok) {
        ebc_tma_kernel<<<blocks, threads>>>(tmap, values, offsets, out);
    } else {
        const int smem = WPB * BUF_BYTES;          // 32 KB
        ebc_pool_kernel<<<blocks, threads, smem>>>(tables, values, offsets, out);
    }
}